// round 10
// baseline (speedup 1.0000x reference)
#include <cuda_runtime.h>

// ---------------- generic fallback state ----------------
__device__ float g_T[8192];

// Compile-time Cayley contraction table for Cl(3,0):
// CIJ[i][j] = reorder_sign(i,j) * sigma(i^j)
__device__ __forceinline__ constexpr float cij_const(int i, int j) {
    constexpr float CIJ[8][8] = {
        { 1.f, 1.f, 1.f,-1.f, 1.f,-1.f,-1.f,-1.f},
        { 1.f, 1.f,-1.f, 1.f,-1.f, 1.f,-1.f,-1.f},
        { 1.f, 1.f, 1.f,-1.f,-1.f, 1.f, 1.f, 1.f},
        {-1.f,-1.f, 1.f,-1.f,-1.f, 1.f,-1.f,-1.f},
        { 1.f, 1.f, 1.f,-1.f, 1.f,-1.f,-1.f,-1.f},
        {-1.f,-1.f, 1.f,-1.f, 1.f,-1.f, 1.f, 1.f},
        {-1.f,-1.f,-1.f, 1.f, 1.f,-1.f,-1.f,-1.f},
        {-1.f,-1.f, 1.f,-1.f,-1.f, 1.f,-1.f,-1.f},
    };
    return CIJ[i][j];
}

__device__ __forceinline__ int bitrev5(int v) {
    return ((v & 1) << 4) | ((v & 2) << 2) | (v & 4) | ((v & 8) >> 2) | ((v & 16) >> 4);
}

__device__ __forceinline__ void stcs4(float* p, float4 v) {
    asm volatile("st.global.cs.v4.f32 [%0], {%1,%2,%3,%4};"
                 :: "l"(p), "f"(v.x), "f"(v.y), "f"(v.z), "f"(v.w) : "memory");
}

// ---------------- specialized fused tile kernel ----------------
// H==512, B==4096, O==128. Grid = 128 blocks = 32 o-tiles x 4 b-tiles,
// 512 threads. Block (ot, bt) computes T[ot*4 .. +3][:] locally (4x compute
// redundancy, zero cross-block sync) then writes out[bt*1024 .., ot*4 ..+3].
__global__ __launch_bounds__(512)
void tile_kernel_s(const float* __restrict__ x,
                   const float* __restrict__ W_in,
                   const float* __restrict__ W_out,
                   float* __restrict__ out,
                   float alpha)
{
    __shared__ float red2[16][32];   // [warp][value]
    __shared__ float Tf[32];         // final T slice: [c*8+i]

    const int tid  = threadIdx.x;
    const int lane = tid & 31;
    const int w    = tid >> 5;
    const int ot = blockIdx.x >> 2;          // 0..31
    const int bt = blockIdx.x & 3;           // 0..3
    const int o0 = ot * 4;
    const int b0 = bt * 1024;

    // ---- prefetch consumer x rows (tid, tid+512) — hides under producer ----
    const float* xp0 = x + (size_t)(b0 + tid) * 8;
    const float* xp1 = x + (size_t)(b0 + tid + 512) * 8;
    float4 xa0 = *(const float4*)xp0;
    float4 xb0 = *(const float4*)(xp0 + 4);
    float4 xa1 = *(const float4*)xp1;
    float4 xb1 = *(const float4*)(xp1 + 4);

    // ---- produce T[o0..o0+3][0..7] : vals[c*8+i], single h per thread ----
    float vals[32];
    {
        const int h = tid;                   // H == 512 == blockDim
        float4 a0 = *(const float4*)(W_in + h * 8);
        float4 a1 = *(const float4*)(W_in + h * 8 + 4);
        float win[8] = {a0.x, a0.y, a0.z, a0.w, a1.x, a1.y, a1.z, a1.w};
        #pragma unroll
        for (int c = 0; c < 4; c++) {
            const float* wp = W_out + ((size_t)(o0 + c) * 512 + h) * 8;
            float4 b0v = *(const float4*)(wp);
            float4 b1v = *(const float4*)(wp + 4);
            float wo[8] = {b0v.x, b0v.y, b0v.z, b0v.w, b1v.x, b1v.y, b1v.z, b1v.w};
            #pragma unroll
            for (int i = 0; i < 8; i++) {
                float s = 0.0f;
                #pragma unroll
                for (int j = 0; j < 8; j++)
                    s = fmaf(cij_const(i, j) > 0.f ? win[j] : -win[j],
                             wo[i ^ j], s);
                vals[c * 8 + i] = s;
            }
        }
    }

    // ---- butterfly reduce 32 values across 32 lanes ----
    // After 5 rounds, lane l holds the lane-sum of value index bitrev5(l).
    {
        int m = 16;
        #pragma unroll
        for (int r = 0; r < 5; r++) {
            const int bit = (lane >> r) & 1;
            #pragma unroll
            for (int k = 0; k < m; k++) {
                float keep = bit ? vals[k + m] : vals[k];
                float send = bit ? vals[k]     : vals[k + m];
                float recv = __shfl_xor_sync(0xffffffff, send, 1 << r);
                vals[k] = keep + recv;
            }
            m >>= 1;
        }
    }
    red2[w][lane] = vals[0];
    __syncthreads();
    if (tid < 32) {
        float s = 0.0f;
        #pragma unroll
        for (int ww = 0; ww < 16; ww++) s += red2[ww][tid];
        Tf[bitrev5(tid)] = alpha * s;
    }
    __syncthreads();

    // ---- consume: 2 rows/thread (tid, tid+512), x already in registers ----
    float tT[32];
    #pragma unroll
    for (int k = 0; k < 32; k++) tT[k] = Tf[k];   // broadcast LDS

    {
        float xv[8] = {xa0.x, xa0.y, xa0.z, xa0.w, xb0.x, xb0.y, xb0.z, xb0.w};
        float s0 = 0, s1 = 0, s2 = 0, s3 = 0;
        #pragma unroll
        for (int i = 0; i < 8; i++) {
            s0 = fmaf(xv[i], tT[i],      s0);
            s1 = fmaf(xv[i], tT[8 + i],  s1);
            s2 = fmaf(xv[i], tT[16 + i], s2);
            s3 = fmaf(xv[i], tT[24 + i], s3);
        }
        stcs4(out + (size_t)(b0 + tid) * 128 + o0, make_float4(s0, s1, s2, s3));
    }
    {
        float xv[8] = {xa1.x, xa1.y, xa1.z, xa1.w, xb1.x, xb1.y, xb1.z, xb1.w};
        float s0 = 0, s1 = 0, s2 = 0, s3 = 0;
        #pragma unroll
        for (int i = 0; i < 8; i++) {
            s0 = fmaf(xv[i], tT[i],      s0);
            s1 = fmaf(xv[i], tT[8 + i],  s1);
            s2 = fmaf(xv[i], tT[16 + i], s2);
            s3 = fmaf(xv[i], tT[24 + i], s3);
        }
        stcs4(out + (size_t)(b0 + tid + 512) * 128 + o0, make_float4(s0, s1, s2, s3));
    }
}

// ---------------- generic tile kernel (O==128, any H/B mult of 4) ----------
__global__ __launch_bounds__(512)
void tile_kernel(const float* __restrict__ x,
                 const float* __restrict__ W_in,
                 const float* __restrict__ W_out,
                 float* __restrict__ out,
                 int H, int rowsPerBlock, float alpha)
{
    __shared__ float red2[16][32];
    __shared__ float Tf[32];

    const int tid  = threadIdx.x;
    const int lane = tid & 31;
    const int w    = tid >> 5;
    const int ot = blockIdx.x >> 2;
    const int bt = blockIdx.x & 3;
    const int o0 = ot * 4;
    const int b0 = bt * rowsPerBlock;

    float vals[32];
    #pragma unroll
    for (int k = 0; k < 32; k++) vals[k] = 0.0f;

    for (int h = tid; h < H; h += 512) {
        float4 a0 = *(const float4*)(W_in + h * 8);
        float4 a1 = *(const float4*)(W_in + h * 8 + 4);
        float win[8] = {a0.x, a0.y, a0.z, a0.w, a1.x, a1.y, a1.z, a1.w};
        #pragma unroll
        for (int c = 0; c < 4; c++) {
            const float* wp = W_out + ((size_t)(o0 + c) * H + h) * 8;
            float4 b0v = *(const float4*)(wp);
            float4 b1v = *(const float4*)(wp + 4);
            float wo[8] = {b0v.x, b0v.y, b0v.z, b0v.w, b1v.x, b1v.y, b1v.z, b1v.w};
            #pragma unroll
            for (int i = 0; i < 8; i++) {
                float s = vals[c * 8 + i];
                #pragma unroll
                for (int j = 0; j < 8; j++)
                    s = fmaf(cij_const(i, j) > 0.f ? win[j] : -win[j],
                             wo[i ^ j], s);
                vals[c * 8 + i] = s;
            }
        }
    }
    {
        int m = 16;
        #pragma unroll
        for (int r = 0; r < 5; r++) {
            const int bit = (lane >> r) & 1;
            #pragma unroll
            for (int k = 0; k < m; k++) {
                float keep = bit ? vals[k + m] : vals[k];
                float send = bit ? vals[k]     : vals[k + m];
                float recv = __shfl_xor_sync(0xffffffff, send, 1 << r);
                vals[k] = keep + recv;
            }
            m >>= 1;
        }
    }
    red2[w][lane] = vals[0];
    __syncthreads();
    if (tid < 32) {
        float s = 0.0f;
        #pragma unroll
        for (int ww = 0; ww < 16; ww++) s += red2[ww][tid];
        Tf[bitrev5(tid)] = alpha * s;
    }
    __syncthreads();

    float tT[32];
    #pragma unroll
    for (int k = 0; k < 32; k++) tT[k] = Tf[k];

    for (int row = tid; row < rowsPerBlock; row += 512) {
        const float* xp = x + (size_t)(b0 + row) * 8;
        float4 xa = *(const float4*)xp;
        float4 xb = *(const float4*)(xp + 4);
        float xv[8] = {xa.x, xa.y, xa.z, xa.w, xb.x, xb.y, xb.z, xb.w};
        float s0 = 0, s1 = 0, s2 = 0, s3 = 0;
        #pragma unroll
        for (int i = 0; i < 8; i++) {
            s0 = fmaf(xv[i], tT[i],      s0);
            s1 = fmaf(xv[i], tT[8 + i],  s1);
            s2 = fmaf(xv[i], tT[16 + i], s2);
            s3 = fmaf(xv[i], tT[24 + i], s3);
        }
        stcs4(out + (size_t)(b0 + row) * 128 + o0, make_float4(s0, s1, s2, s3));
    }
}

// ---------------- generic two-kernel fallback (any O/H/B) ----------------
__device__ __forceinline__ void gp_accum(float acc[8],
                                         const float win[8],
                                         const float wout[8])
{
    #pragma unroll
    for (int i = 0; i < 8; i++) {
        float s = acc[i];
        #pragma unroll
        for (int j = 0; j < 8; j++)
            s = fmaf(cij_const(i, j) > 0.f ? win[j] : -win[j], wout[i ^ j], s);
        acc[i] = s;
    }
}

__global__ void compute_T_generic(const float* __restrict__ W_in,
                                  const float* __restrict__ W_out,
                                  int H, float alpha)
{
    const int o = blockIdx.x;
    const int tid = threadIdx.x;
    float acc[8];
    #pragma unroll
    for (int i = 0; i < 8; i++) acc[i] = 0.0f;
    const float* woutBase = W_out + (size_t)o * H * 8;
    for (int h = tid; h < H; h += blockDim.x) {
        float4 a0 = *(const float4*)(W_in + h * 8);
        float4 a1 = *(const float4*)(W_in + h * 8 + 4);
        float4 b0 = *(const float4*)(woutBase + h * 8);
        float4 b1 = *(const float4*)(woutBase + h * 8 + 4);
        float win[8]  = {a0.x, a0.y, a0.z, a0.w, a1.x, a1.y, a1.z, a1.w};
        float wout[8] = {b0.x, b0.y, b0.z, b0.w, b1.x, b1.y, b1.z, b1.w};
        gp_accum(acc, win, wout);
    }
    #pragma unroll
    for (int i = 0; i < 8; i++)
        #pragma unroll
        for (int off = 16; off > 0; off >>= 1)
            acc[i] += __shfl_xor_sync(0xffffffff, acc[i], off);
    __shared__ float red[8][8];
    const int lane = tid & 31, w = tid >> 5;
    const int nw = blockDim.x >> 5;
    if (lane == 0) {
        #pragma unroll
        for (int i = 0; i < 8; i++) red[w][i] = acc[i];
    }
    __syncthreads();
    if (tid < 8) {
        float s = 0.0f;
        for (int ww = 0; ww < nw; ww++) s += red[ww][tid];
        g_T[o * 8 + tid] = alpha * s;
    }
}

__global__ void finalize_generic_kernel(const float* __restrict__ x,
                                        float* __restrict__ out, int O)
{
    extern __shared__ float Tg[];
    for (int idx = threadIdx.x; idx < O * 8; idx += blockDim.x) {
        int o = idx >> 3, i = idx & 7;
        Tg[i * O + o] = g_T[idx];
    }
    __syncthreads();
    const int b = blockIdx.x;
    float4 x0 = *(const float4*)(x + b * 8);
    float4 x1 = *(const float4*)(x + b * 8 + 4);
    for (int o = threadIdx.x; o < O; o += blockDim.x) {
        float s = x0.x * Tg[o]         + x0.y * Tg[O + o]
                + x0.z * Tg[2 * O + o] + x0.w * Tg[3 * O + o]
                + x1.x * Tg[4 * O + o] + x1.y * Tg[5 * O + o]
                + x1.z * Tg[6 * O + o] + x1.w * Tg[7 * O + o];
        out[(size_t)b * O + o] = s;
    }
}

extern "C" void kernel_launch(void* const* d_in, const int* in_sizes, int n_in,
                              void* d_out, int out_size)
{
    const float* x     = (const float*)d_in[0];  // [B,8]
    const float* W_in  = (const float*)d_in[1];  // [H,1,8]
    const float* W_out = (const float*)d_in[2];  // [O,H,8]

    const int B = in_sizes[0] / 8;
    const int H = in_sizes[1] / 8;
    const int O = in_sizes[2] / (H * 8);

    // alpha = 1 - (1-dt)^n_free, dt=0.1, n_free=10
    double p = 1.0;
    for (int i = 0; i < 10; i++) p *= 0.9;
    const float alpha = (float)(1.0 - p);

    if (O == 128 && H == 512 && B == 4096) {
        tile_kernel_s<<<128, 512>>>(x, W_in, W_out, (float*)d_out, alpha);
    } else if (O == 128 && (B % 4) == 0) {
        tile_kernel<<<128, 512>>>(x, W_in, W_out, (float*)d_out,
                                  H, B / 4, alpha);
    } else {
        compute_T_generic<<<O, 256>>>(W_in, W_out, H, alpha);
        finalize_generic_kernel<<<B, 128, O * 8 * sizeof(float)>>>(x, (float*)d_out, O);
    }
}

// round 11
// speedup vs baseline: 1.0264x; 1.0264x over previous
#include <cuda_runtime.h>
#include <cstdint>

// ---------------- generic fallback state ----------------
__device__ float g_T[8192];

// Compile-time Cayley contraction table for Cl(3,0):
// CIJ[i][j] = reorder_sign(i,j) * sigma(i^j)
__device__ __forceinline__ constexpr float cij_const(int i, int j) {
    constexpr float CIJ[8][8] = {
        { 1.f, 1.f, 1.f,-1.f, 1.f,-1.f,-1.f,-1.f},
        { 1.f, 1.f,-1.f, 1.f,-1.f, 1.f,-1.f,-1.f},
        { 1.f, 1.f, 1.f,-1.f,-1.f, 1.f, 1.f, 1.f},
        {-1.f,-1.f, 1.f,-1.f,-1.f, 1.f,-1.f,-1.f},
        { 1.f, 1.f, 1.f,-1.f, 1.f,-1.f,-1.f,-1.f},
        {-1.f,-1.f, 1.f,-1.f, 1.f,-1.f, 1.f, 1.f},
        {-1.f,-1.f,-1.f, 1.f, 1.f,-1.f,-1.f,-1.f},
        {-1.f,-1.f, 1.f,-1.f,-1.f, 1.f,-1.f,-1.f},
    };
    return CIJ[i][j];
}

__device__ __forceinline__ int bitrev5(int v) {
    return ((v & 1) << 4) | ((v & 2) << 2) | (v & 4) | ((v & 8) >> 2) | ((v & 16) >> 4);
}

__device__ __forceinline__ void stcs4(float* p, float4 v) {
    asm volatile("st.global.cs.v4.f32 [%0], {%1,%2,%3,%4};"
                 :: "l"(p), "f"(v.x), "f"(v.y), "f"(v.z), "f"(v.w) : "memory");
}

__device__ __forceinline__ uint32_t smem_u32(const void* p) {
    uint32_t a;
    asm("{ .reg .u64 t; cvta.to.shared.u64 t, %1; cvt.u32.u64 %0, t; }"
        : "=r"(a) : "l"(p));
    return a;
}

__device__ __forceinline__ void st_shared_cluster_f32(uint32_t local_addr,
                                                      int target_rank, float v) {
    asm volatile(
        "{\n\t"
        ".reg .b32 ra;\n\t"
        "mapa.shared::cluster.u32 ra, %0, %1;\n\t"
        "st.shared::cluster.f32 [ra], %2;\n\t"
        "}"
        :: "r"(local_addr), "r"(target_rank), "f"(v) : "memory");
}

// ---------------- clustered tile kernel (O=128, H=512, B=4096) ----------------
// 32 clusters x 4 CTAs. Cluster = o-tile of 4 (o0 = cid*4). CTA rank r:
//   produce: partial T[o0..o0+3][:] over h-slice [r*128, r*128+128)  (64 FMA/thr)
//   exchange: DSMEM all-reduce of 32 partials across the 4 ranks
//   consume: rows [r*1024, (r+1)*1024), 2 rows/thread, streaming stores.
// Zero chip-wide redundancy: every (o,h) term computed exactly once.
__global__ __launch_bounds__(512) __cluster_dims__(4, 1, 1)
void cluster_kernel(const float* __restrict__ x,
                    const float* __restrict__ W_in,
                    const float* __restrict__ W_out,
                    float* __restrict__ out,
                    float alpha)
{
    __shared__ float red2[16][4][8];   // [warp][c][i]
    __shared__ float part_s[32];       // this CTA's partial, k = c*8+i
    __shared__ float pbuf[4][32];      // partials from each rank (via DSMEM)
    __shared__ float Tf[32];           // final T slice

    const int tid  = threadIdx.x;
    const int lane = tid & 31;
    const int w    = tid >> 5;
    uint32_t rank;
    asm("mov.u32 %0, %%cluster_ctarank;" : "=r"(rank));
    const int o0 = (blockIdx.x >> 2) * 4;
    const int b0 = (int)rank * 1024;

    // ---- prefetch consumer x rows (tid, tid+512): hides under producer ----
    const float* xp0 = x + (size_t)(b0 + tid) * 8;
    const float* xp1 = x + (size_t)(b0 + tid + 512) * 8;
    float4 xa0 = *(const float4*)xp0;
    float4 xb0 = *(const float4*)(xp0 + 4);
    float4 xa1 = *(const float4*)xp1;
    float4 xb1 = *(const float4*)(xp1 + 4);

    // ---- produce partial T: thread handles (h, c) ----
    float vals[8];
    {
        const int h = (int)rank * 128 + (tid >> 2);
        const int c = tid & 3;
        float4 a0 = *(const float4*)(W_in + h * 8);
        float4 a1 = *(const float4*)(W_in + h * 8 + 4);
        float win[8] = {a0.x, a0.y, a0.z, a0.w, a1.x, a1.y, a1.z, a1.w};
        const float* wp = W_out + ((size_t)(o0 + c) * 512 + h) * 8;
        float4 b0v = *(const float4*)(wp);
        float4 b1v = *(const float4*)(wp + 4);
        float wo[8] = {b0v.x, b0v.y, b0v.z, b0v.w, b1v.x, b1v.y, b1v.z, b1v.w};
        #pragma unroll
        for (int i = 0; i < 8; i++) {
            float s = 0.0f;
            #pragma unroll
            for (int j = 0; j < 8; j++)
                s = fmaf(cij_const(i, j) > 0.f ? win[j] : -win[j], wo[i ^ j], s);
            vals[i] = s;
        }
    }
    // butterfly over lanes sharing c (bits 2,3,4): 24 shuffles
    #pragma unroll
    for (int off = 4; off <= 16; off <<= 1)
        #pragma unroll
        for (int i = 0; i < 8; i++)
            vals[i] += __shfl_xor_sync(0xffffffff, vals[i], off);
    if (lane < 4) {
        #pragma unroll
        for (int i = 0; i < 8; i++) red2[w][lane][i] = vals[i];
    }
    __syncthreads();
    if (tid < 32) {                      // k = tid = c*8+i
        const int c = tid >> 3, i = tid & 7;
        float s = 0.0f;
        #pragma unroll
        for (int ww = 0; ww < 16; ww++) s += red2[ww][c][i];
        part_s[tid] = alpha * s;
    }
    __syncthreads();

    // ---- DSMEM all-reduce: send my partial to slot[rank] of every CTA ----
    if (tid < 128) {
        const int rr = tid >> 5;         // target rank
        const int k  = tid & 31;
        uint32_t la = smem_u32(&pbuf[rank][k]);
        st_shared_cluster_f32(la, rr, part_s[k]);
    }
    asm volatile("barrier.cluster.arrive.aligned;" ::: "memory");
    asm volatile("barrier.cluster.wait.aligned;"   ::: "memory");

    if (tid < 32)
        Tf[tid] = pbuf[0][tid] + pbuf[1][tid] + pbuf[2][tid] + pbuf[3][tid];
    __syncthreads();

    // ---- consume: 2 rows/thread, x already in registers ----
    float tT[32];
    #pragma unroll
    for (int k = 0; k < 32; k++) tT[k] = Tf[k];   // broadcast LDS

    {
        float xv[8] = {xa0.x, xa0.y, xa0.z, xa0.w, xb0.x, xb0.y, xb0.z, xb0.w};
        float s0 = 0, s1 = 0, s2 = 0, s3 = 0;
        #pragma unroll
        for (int i = 0; i < 8; i++) {
            s0 = fmaf(xv[i], tT[i],      s0);
            s1 = fmaf(xv[i], tT[8 + i],  s1);
            s2 = fmaf(xv[i], tT[16 + i], s2);
            s3 = fmaf(xv[i], tT[24 + i], s3);
        }
        stcs4(out + (size_t)(b0 + tid) * 128 + o0, make_float4(s0, s1, s2, s3));
    }
    {
        float xv[8] = {xa1.x, xa1.y, xa1.z, xa1.w, xb1.x, xb1.y, xb1.z, xb1.w};
        float s0 = 0, s1 = 0, s2 = 0, s3 = 0;
        #pragma unroll
        for (int i = 0; i < 8; i++) {
            s0 = fmaf(xv[i], tT[i],      s0);
            s1 = fmaf(xv[i], tT[8 + i],  s1);
            s2 = fmaf(xv[i], tT[16 + i], s2);
            s3 = fmaf(xv[i], tT[24 + i], s3);
        }
        stcs4(out + (size_t)(b0 + tid + 512) * 128 + o0, make_float4(s0, s1, s2, s3));
    }
    // cluster barrier before exit: no CTA may leave while peers might still
    // read nothing from it (all DSMEM traffic already synced above; this is
    // implicit on sm_90+ cluster exit, no extra barrier needed).
}

// ---------------- non-cluster tile kernel (O==128, any H mult, B%4==0) ------
__global__ __launch_bounds__(512)
void tile_kernel(const float* __restrict__ x,
                 const float* __restrict__ W_in,
                 const float* __restrict__ W_out,
                 float* __restrict__ out,
                 int H, int rowsPerBlock, float alpha)
{
    __shared__ float red2[16][32];
    __shared__ float Tf[32];

    const int tid  = threadIdx.x;
    const int lane = tid & 31;
    const int w    = tid >> 5;
    const int ot = blockIdx.x >> 2;
    const int bt = blockIdx.x & 3;
    const int o0 = ot * 4;
    const int b0 = bt * rowsPerBlock;

    float vals[32];
    #pragma unroll
    for (int k = 0; k < 32; k++) vals[k] = 0.0f;

    for (int h = tid; h < H; h += 512) {
        float4 a0 = *(const float4*)(W_in + h * 8);
        float4 a1 = *(const float4*)(W_in + h * 8 + 4);
        float win[8] = {a0.x, a0.y, a0.z, a0.w, a1.x, a1.y, a1.z, a1.w};
        #pragma unroll
        for (int c = 0; c < 4; c++) {
            const float* wp = W_out + ((size_t)(o0 + c) * H + h) * 8;
            float4 b0v = *(const float4*)(wp);
            float4 b1v = *(const float4*)(wp + 4);
            float wo[8] = {b0v.x, b0v.y, b0v.z, b0v.w, b1v.x, b1v.y, b1v.z, b1v.w};
            #pragma unroll
            for (int i = 0; i < 8; i++) {
                float s = vals[c * 8 + i];
                #pragma unroll
                for (int j = 0; j < 8; j++)
                    s = fmaf(cij_const(i, j) > 0.f ? win[j] : -win[j],
                             wo[i ^ j], s);
                vals[c * 8 + i] = s;
            }
        }
    }
    {
        int m = 16;
        #pragma unroll
        for (int r = 0; r < 5; r++) {
            const int bit = (lane >> r) & 1;
            #pragma unroll
            for (int k = 0; k < m; k++) {
                float keep = bit ? vals[k + m] : vals[k];
                float send = bit ? vals[k]     : vals[k + m];
                float recv = __shfl_xor_sync(0xffffffff, send, 1 << r);
                vals[k] = keep + recv;
            }
            m >>= 1;
        }
    }
    red2[w][lane] = vals[0];
    __syncthreads();
    if (tid < 32) {
        float s = 0.0f;
        #pragma unroll
        for (int ww = 0; ww < 16; ww++) s += red2[ww][tid];
        Tf[bitrev5(tid)] = alpha * s;
    }
    __syncthreads();

    float tT[32];
    #pragma unroll
    for (int k = 0; k < 32; k++) tT[k] = Tf[k];

    for (int row = tid; row < rowsPerBlock; row += 512) {
        const float* xp = x + (size_t)(b0 + row) * 8;
        float4 xa = *(const float4*)xp;
        float4 xb = *(const float4*)(xp + 4);
        float xv[8] = {xa.x, xa.y, xa.z, xa.w, xb.x, xb.y, xb.z, xb.w};
        float s0 = 0, s1 = 0, s2 = 0, s3 = 0;
        #pragma unroll
        for (int i = 0; i < 8; i++) {
            s0 = fmaf(xv[i], tT[i],      s0);
            s1 = fmaf(xv[i], tT[8 + i],  s1);
            s2 = fmaf(xv[i], tT[16 + i], s2);
            s3 = fmaf(xv[i], tT[24 + i], s3);
        }
        stcs4(out + (size_t)(b0 + row) * 128 + o0, make_float4(s0, s1, s2, s3));
    }
}

// ---------------- generic two-kernel fallback (any O/H/B) ----------------
__device__ __forceinline__ void gp_accum(float acc[8],
                                         const float win[8],
                                         const float wout[8])
{
    #pragma unroll
    for (int i = 0; i < 8; i++) {
        float s = acc[i];
        #pragma unroll
        for (int j = 0; j < 8; j++)
            s = fmaf(cij_const(i, j) > 0.f ? win[j] : -win[j], wout[i ^ j], s);
        acc[i] = s;
    }
}

__global__ void compute_T_generic(const float* __restrict__ W_in,
                                  const float* __restrict__ W_out,
                                  int H, float alpha)
{
    const int o = blockIdx.x;
    const int tid = threadIdx.x;
    float acc[8];
    #pragma unroll
    for (int i = 0; i < 8; i++) acc[i] = 0.0f;
    const float* woutBase = W_out + (size_t)o * H * 8;
    for (int h = tid; h < H; h += blockDim.x) {
        float4 a0 = *(const float4*)(W_in + h * 8);
        float4 a1 = *(const float4*)(W_in + h * 8 + 4);
        float4 b0 = *(const float4*)(woutBase + h * 8);
        float4 b1 = *(const float4*)(woutBase + h * 8 + 4);
        float win[8]  = {a0.x, a0.y, a0.z, a0.w, a1.x, a1.y, a1.z, a1.w};
        float wout[8] = {b0.x, b0.y, b0.z, b0.w, b1.x, b1.y, b1.z, b1.w};
        gp_accum(acc, win, wout);
    }
    #pragma unroll
    for (int i = 0; i < 8; i++)
        #pragma unroll
        for (int off = 16; off > 0; off >>= 1)
            acc[i] += __shfl_xor_sync(0xffffffff, acc[i], off);
    __shared__ float red[8][8];
    const int lane = tid & 31, w = tid >> 5;
    const int nw = blockDim.x >> 5;
    if (lane == 0) {
        #pragma unroll
        for (int i = 0; i < 8; i++) red[w][i] = acc[i];
    }
    __syncthreads();
    if (tid < 8) {
        float s = 0.0f;
        for (int ww = 0; ww < nw; ww++) s += red[ww][tid];
        g_T[o * 8 + tid] = alpha * s;
    }
}

__global__ void finalize_generic_kernel(const float* __restrict__ x,
                                        float* __restrict__ out, int O)
{
    extern __shared__ float Tg[];
    for (int idx = threadIdx.x; idx < O * 8; idx += blockDim.x) {
        int o = idx >> 3, i = idx & 7;
        Tg[i * O + o] = g_T[idx];
    }
    __syncthreads();
    const int b = blockIdx.x;
    float4 x0 = *(const float4*)(x + b * 8);
    float4 x1 = *(const float4*)(x + b * 8 + 4);
    for (int o = threadIdx.x; o < O; o += blockDim.x) {
        float s = x0.x * Tg[o]         + x0.y * Tg[O + o]
                + x0.z * Tg[2 * O + o] + x0.w * Tg[3 * O + o]
                + x1.x * Tg[4 * O + o] + x1.y * Tg[5 * O + o]
                + x1.z * Tg[6 * O + o] + x1.w * Tg[7 * O + o];
        out[(size_t)b * O + o] = s;
    }
}

extern "C" void kernel_launch(void* const* d_in, const int* in_sizes, int n_in,
                              void* d_out, int out_size)
{
    const float* x     = (const float*)d_in[0];  // [B,8]
    const float* W_in  = (const float*)d_in[1];  // [H,1,8]
    const float* W_out = (const float*)d_in[2];  // [O,H,8]

    const int B = in_sizes[0] / 8;
    const int H = in_sizes[1] / 8;
    const int O = in_sizes[2] / (H * 8);

    // alpha = 1 - (1-dt)^n_free, dt=0.1, n_free=10
    double p = 1.0;
    for (int i = 0; i < 10; i++) p *= 0.9;
    const float alpha = (float)(1.0 - p);

    if (O == 128 && H == 512 && B == 4096) {
        cluster_kernel<<<128, 512>>>(x, W_in, W_out, (float*)d_out, alpha);
    } else if (O == 128 && (B % 4) == 0) {
        tile_kernel<<<128, 512>>>(x, W_in, W_out, (float*)d_out,
                                  H, B / 4, alpha);
    } else {
        compute_T_generic<<<O, 256>>>(W_in, W_out, H, alpha);
        finalize_generic_kernel<<<B, 128, O * 8 * sizeof(float)>>>(x, (float*)d_out, O);
    }
}